// round 4
// baseline (speedup 1.0000x reference)
#include <cuda_runtime.h>
#include <cstdint>

#define T_LEN 131072
#define D_X 16
#define D_L 8

// d_out layout (flat concat of reference tuple, all float32)
#define OFF_RECON 0
#define OFF_PRED  (T_LEN * D_X)
#define OFF_LMP   (2 * T_LEN * D_X)
#define OFF_LVP   (OFF_LMP + 2 * T_LEN * D_L)
#define OFF_CT    (OFF_LVP + 2 * T_LEN * D_L)
#define OFF_CT1   (OFF_CT + T_LEN * D_X * D_L)

// ---------------------------------------------------------------------------
// Packed fp32x2 ops (Blackwell)
// ---------------------------------------------------------------------------
__device__ __forceinline__ float2 ffma2(float2 a, float2 b, float2 c) {
    float2 d;
    asm("{\n\t"
        ".reg .b64 ra, rb, rc, rd;\n\t"
        "mov.b64 ra, {%2, %3};\n\t"
        "mov.b64 rb, {%4, %5};\n\t"
        "mov.b64 rc, {%6, %7};\n\t"
        "fma.rn.f32x2 rd, ra, rb, rc;\n\t"
        "mov.b64 {%0, %1}, rd;\n\t"
        "}"
        : "=f"(d.x), "=f"(d.y)
        : "f"(a.x), "f"(a.y), "f"(b.x), "f"(b.y), "f"(c.x), "f"(c.y));
    return d;
}
__device__ __forceinline__ float2 fadd2(float2 a, float2 b) {
    float2 d;
    asm("{\n\t"
        ".reg .b64 ra, rb, rd;\n\t"
        "mov.b64 ra, {%2, %3};\n\t"
        "mov.b64 rb, {%4, %5};\n\t"
        "add.rn.f32x2 rd, ra, rb;\n\t"
        "mov.b64 {%0, %1}, rd;\n\t"
        "}"
        : "=f"(d.x), "=f"(d.y)
        : "f"(a.x), "f"(a.y), "f"(b.x), "f"(b.y));
    return d;
}
__device__ __forceinline__ float2 fmul2(float2 a, float2 b) {
    float2 d;
    asm("{\n\t"
        ".reg .b64 ra, rb, rd;\n\t"
        "mov.b64 ra, {%2, %3};\n\t"
        "mov.b64 rb, {%4, %5};\n\t"
        "mul.rn.f32x2 rd, ra, rb;\n\t"
        "mov.b64 {%0, %1}, rd;\n\t"
        "}"
        : "=f"(d.x), "=f"(d.y)
        : "f"(a.x), "f"(a.y), "f"(b.x), "f"(b.y));
    return d;
}

// ---------------------------------------------------------------------------
// Preprocessed decoder weights (device-global scratch; no allocation).
// ---------------------------------------------------------------------------
__device__ __align__(16) float g_w0t[D_X * 64 * 32];  // [n][j][f]
__device__ __align__(16) float g_w12[D_X * 64];       // collapsed lw1@lw2
__device__ __align__(16) float g_beff[D_X];           // lb1@lw2 + lb2

__global__ void prep_kernel(const float* __restrict__ lw0,
                            const float* __restrict__ lw1,
                            const float* __restrict__ lw2,
                            const float* __restrict__ lb0,
                            const float* __restrict__ lb1,
                            const float* __restrict__ lb2,
                            float* __restrict__ out) {
    int tid = threadIdx.x;          // 1024 threads: (n, j)
    int n = tid >> 6;
    int j = tid & 63;
#pragma unroll
    for (int f = 0; f < 32; f++)
        g_w0t[(n * 64 + j) * 32 + f] = lw0[(n * 32 + f) * 64 + j];
    float acc = 0.f;
#pragma unroll 8
    for (int o = 0; o < 64; o++)
        acc = fmaf(lw1[(n * 64 + j) * 64 + o], lw2[n * 64 + o], acc);
    g_w12[n * 64 + j] = acc;
    if (j == 0) {
        float b = lb2[n];
        for (int o = 0; o < 64; o++)
            b = fmaf(lb1[n * 64 + o], lw2[n * 64 + o], b);
        g_beff[n] = b;
    }
    __syncthreads();
    // pred[0]: features are all-zero -> h = relu(lb0), out = relu(h.w12 + beff)
    if (j == 0) {
        float s = g_beff[n];
        for (int o = 0; o < 64; o++) {
            float h = fmaxf(lb0[n * 64 + o], 0.f);
            s = fmaf(h, g_w12[n * 64 + o], s);
        }
        out[OFF_PRED + n] = fmaxf(s, 0.f);
    }
}

// ---------------------------------------------------------------------------
// enc layers 0+1 (packed block: w0[8] b0[8] w1[64] b1[8]) -> h1[8]
// ---------------------------------------------------------------------------
__device__ __forceinline__ void enc01(float s, const float* __restrict__ w,
                                      float* __restrict__ h1) {
    float h0[8];
#pragma unroll
    for (int i = 0; i < 8; i++) {
        float v = fmaf(s, w[i], w[8 + i]);
        h0[i] = v > 0.f ? v : 0.01f * v;
    }
#pragma unroll
    for (int j = 0; j < 8; j++) {
        float a = 0.f;
#pragma unroll
        for (int i = 0; i < 8; i++) a = fmaf(h0[i], w[16 + i * 8 + j], a);
        a += w[80 + j];
        h1[j] = a > 0.f ? a : 0.01f * a;
    }
}

// ---------------------------------------------------------------------------
// Head: relu(x @ W1 + b1) @ W2 + b2   (8->128->8), one row
// ---------------------------------------------------------------------------
__device__ __forceinline__ void head_fn(const float* __restrict__ x8,
                                        const float* __restrict__ w1t,  // [j][k]
                                        const float* __restrict__ b1,
                                        const float* __restrict__ w2,   // [j][o]
                                        const float* __restrict__ b2,
                                        float* __restrict__ dst) {
    float4 xa = *(const float4*)&x8[0];
    float4 xb = *(const float4*)&x8[4];
    float2 xx0 = make_float2(xa.x, xa.y), xx1 = make_float2(xa.z, xa.w);
    float2 xx2 = make_float2(xb.x, xb.y), xx3 = make_float2(xb.z, xb.w);
    float4 b2a = *(const float4*)&b2[0];
    float4 b2b = *(const float4*)&b2[4];
    float2 o0 = make_float2(b2a.x, b2a.y), o1 = make_float2(b2a.z, b2a.w);
    float2 o2 = make_float2(b2b.x, b2b.y), o3 = make_float2(b2b.z, b2b.w);
    const float2 zz = make_float2(0.f, 0.f);
#pragma unroll 4
    for (int j = 0; j < 128; j++) {
        float4 wA = *(const float4*)&w1t[j * 8];
        float4 wB = *(const float4*)&w1t[j * 8 + 4];
        float2 a0 = ffma2(xx0, make_float2(wA.x, wA.y), zz);
        float2 a1 = ffma2(xx2, make_float2(wB.x, wB.y), zz);
        a0 = ffma2(xx1, make_float2(wA.z, wA.w), a0);
        a1 = ffma2(xx3, make_float2(wB.z, wB.w), a1);
        float h = a0.x + a0.y + a1.x + a1.y + b1[j];
        h = fmaxf(h, 0.f);
        float2 hh = make_float2(h, h);
        float4 u = *(const float4*)&w2[j * 8];
        float4 v = *(const float4*)&w2[j * 8 + 4];
        o0 = ffma2(hh, make_float2(u.x, u.y), o0);
        o1 = ffma2(hh, make_float2(u.z, u.w), o1);
        o2 = ffma2(hh, make_float2(v.x, v.y), o2);
        o3 = ffma2(hh, make_float2(v.z, v.w), o3);
    }
    *(float4*)&dst[0] = make_float4(o0.x, o0.y, o1.x, o1.y);
    *(float4*)&dst[4] = make_float4(o2.x, o2.y, o3.x, o3.y);
}

// ---------------------------------------------------------------------------
// Mega kernel, 4-way node split: blockIdx.y = quarter q (nodes 4q..4q+3).
// Thread t computes recon(t), pred(t+1) for its quarter's nodes, plus
// head row q of [(lm,t),(lm,T+t),(lv,t),(lv,T+t)].
// ---------------------------------------------------------------------------
#define QB 256
#define QGX (T_LEN / QB)   // 512

// smem float offsets
#define S_W0    0                    // 4*64*32 = 8192
#define S_BW    8192                 // [ln][j] (b0, w12) pairs: 512
#define S_BEFF  8704                 // 4
#define S_CL01  8708                 // 88
#define S_PL01  8796                 // 88
#define S_CW2T  8884                 // [ln][k][i] 256
#define S_CB2   9140                 // 32
#define S_PW2T  9172                 // 256
#define S_PB2   9428                 // 32
#define S_HW1T  9460                 // 1024
#define S_HB1   10484                // 128
#define S_HW2   10612                // 1024
#define S_HB2   11636                // 8
#define S_V     11644                // 8 pair-slots * QB * 2 = 4096
#define S_TOT   (S_V + 16 * QB)      // 15740 floats
#define MEGA_SMEM_BYTES (S_TOT * 4)  // 62960 B -> 3 CTAs/SM

__global__ __launch_bounds__(QB, 3)
void mega_kernel(const float* __restrict__ lm, const float* __restrict__ lv,
                 const float* __restrict__ Tin,
                 const float* cw0, const float* cb0, const float* cw1,
                 const float* cb1, const float* cw2, const float* cb2,
                 const float* pw0, const float* pb0, const float* pw1,
                 const float* pb1, const float* pw2, const float* pb2,
                 const float* fmw1, const float* fmb1,
                 const float* fmw2, const float* fmb2,
                 const float* fvw1, const float* fvb1,
                 const float* fvw2, const float* fvb2,
                 const float* __restrict__ lb0,
                 float* __restrict__ out) {
    extern __shared__ __align__(16) float smem[];
    const int tid = threadIdx.x;
    const int q = blockIdx.y;
    const int nb = q * 4;             // node base

    // ---- cooperative smem fill ----
    for (int i = tid; i < (4 * 64 * 32) / 4; i += QB)
        ((float4*)(smem + S_W0))[i] = ((const float4*)(g_w0t + nb * 2048))[i];
    for (int i = tid; i < 256; i += QB) {
        smem[S_BW + 2 * i]     = lb0[nb * 64 + i];
        smem[S_BW + 2 * i + 1] = g_w12[nb * 64 + i];
    }
    if (tid < 4) smem[S_BEFF + tid] = g_beff[nb + tid];
    for (int i = tid; i < 88; i += QB) {
        float v, u;
        if (i < 8)       { v = cw0[i];      u = pw0[i];      }
        else if (i < 16) { v = cb0[i - 8];  u = pb0[i - 8];  }
        else if (i < 80) { v = cw1[i - 16]; u = pw1[i - 16]; }
        else             { v = cb1[i - 80]; u = pb1[i - 80]; }
        smem[S_CL01 + i] = v;
        smem[S_PL01 + i] = u;
    }
    for (int i = tid; i < 256; i += QB) {
        int ln = i >> 6, k = (i >> 3) & 7, ii = i & 7;
        int src = ii * 128 + (nb + ln) * 8 + k;
        smem[S_CW2T + i] = cw2[src];
        smem[S_PW2T + i] = pw2[src];
    }
    for (int i = tid; i < 32; i += QB) {
        smem[S_CB2 + i] = cb2[nb * 8 + i];
        smem[S_PB2 + i] = pb2[nb * 8 + i];
    }
    {
        const float* hw1 = (q >> 1) ? fvw1 : fmw1;
        const float* hw2 = (q >> 1) ? fvw2 : fmw2;
        const float* hb1 = (q >> 1) ? fvb1 : fmb1;
        const float* hb2 = (q >> 1) ? fvb2 : fmb2;
        for (int i = tid; i < 1024; i += QB) {
            int j = i >> 3, k = i & 7;
            smem[S_HW1T + i] = hw1[k * 128 + j];
            smem[S_HW2 + i]  = hw2[i];
        }
        if (tid < 128) smem[S_HB1 + tid] = hb1[tid];
        if (tid < 8)   smem[S_HB2 + tid] = hb2[tid];
    }
    __syncthreads();

    const int t = blockIdx.x * QB + tid;

    // ---- enc phase: Ct (4 nodes, binarized + mask) and Ct1 (4 nodes) ----
    float s = Tin[t];
    unsigned mbytes = 0;              // 4 bytes of per-node masks
    {
        float h1c[8];
        enc01(s, smem + S_CL01, h1c);
        float* ctdst = out + OFF_CT + (size_t)t * 128 + nb * 8;
#pragma unroll
        for (int ln = 0; ln < 4; ln++) {
            float vals[8];
#pragma unroll
            for (int k = 0; k < 8; k++) {
                const float* w = smem + S_CW2T + (ln * 8 + k) * 8;
                float a = 0.f;
#pragma unroll
                for (int i = 0; i < 8; i++) a = fmaf(h1c[i], w[i], a);
                a += smem[S_CB2 + ln * 8 + k];
                bool on = !(a < 0.1f);
                vals[k] = on ? 1.f : 0.f;
                if (on) mbytes |= 1u << (ln * 8 + k);
            }
            *(float4*)&ctdst[ln * 8]     = make_float4(vals[0], vals[1], vals[2], vals[3]);
            *(float4*)&ctdst[ln * 8 + 4] = make_float4(vals[4], vals[5], vals[6], vals[7]);
        }
    }
    {
        float h1q[8];
        enc01(s, smem + S_PL01, h1q);
        float* c1dst = out + OFF_CT1 + (size_t)t * 128 + nb * 8;
#pragma unroll
        for (int ln = 0; ln < 4; ln++) {
            float vals[8];
#pragma unroll
            for (int k = 0; k < 8; k++) {
                const float* w = smem + S_PW2T + (ln * 8 + k) * 8;
                float a = 0.f;
#pragma unroll
                for (int i = 0; i < 8; i++) a = fmaf(h1q[i], w[i], a);
                vals[k] = a + smem[S_PB2 + ln * 8 + k];
            }
            *(float4*)&c1dst[ln * 8]     = make_float4(vals[0], vals[1], vals[2], vals[3]);
            *(float4*)&c1dst[ln * 8 + 4] = make_float4(vals[4], vals[5], vals[6], vals[7]);
        }
    }
    const bool hasP = (t + 1 < T_LEN);
    float h1p[8];
    {
        float s2 = hasP ? Tin[t + 1] : 0.f;
        enc01(s2, smem + S_PL01, h1p);
    }

    // ---- head phase: quarter q handles one of the 4 rows ----
    {
        const float* x = (q >> 1) ? lv : lm;
        float* hdst = out + ((q >> 1) ? OFF_LVP : OFF_LMP);
        size_t row = (q & 1) ? ((size_t)T_LEN + t) : (size_t)t;
        head_fn(x + row * 8, smem + S_HW1T, smem + S_HB1, smem + S_HW2,
                smem + S_HB2, hdst + row * 8);
    }

    // ---- decode setup: M in regs, V staged to per-thread smem (float2) ----
    const float4* lm4 = (const float4*)lm;
    const float4* lv4 = (const float4*)lv;
    float2 M[8];
    {
        float4 a0 = lm4[(size_t)t * 2], a1 = lm4[(size_t)t * 2 + 1];
        float4 b0 = lm4[((size_t)T_LEN + t) * 2], b1 = lm4[((size_t)T_LEN + t) * 2 + 1];
        M[0] = make_float2(a0.x, b0.x); M[1] = make_float2(a0.y, b0.y);
        M[2] = make_float2(a0.z, b0.z); M[3] = make_float2(a0.w, b0.w);
        M[4] = make_float2(a1.x, b1.x); M[5] = make_float2(a1.y, b1.y);
        M[6] = make_float2(a1.z, b1.z); M[7] = make_float2(a1.w, b1.w);
        float4 c0 = lv4[(size_t)t * 2], c1 = lv4[(size_t)t * 2 + 1];
        float4 d0 = lv4[((size_t)T_LEN + t) * 2], d1 = lv4[((size_t)T_LEN + t) * 2 + 1];
        float2* sv = (float2*)(smem + S_V);
        // pair-slot k at sv[k*QB + tid]
        sv[0 * QB + tid] = make_float2(c0.x, d0.x);
        sv[1 * QB + tid] = make_float2(c0.y, d0.y);
        sv[2 * QB + tid] = make_float2(c0.z, d0.z);
        sv[3 * QB + tid] = make_float2(c0.w, d0.w);
        sv[4 * QB + tid] = make_float2(c1.x, d1.x);
        sv[5 * QB + tid] = make_float2(c1.y, d1.y);
        sv[6 * QB + tid] = make_float2(c1.z, d1.z);
        sv[7 * QB + tid] = make_float2(c1.w, d1.w);
    }

    const float2 zz = make_float2(0.f, 0.f);
    const float2* sv = (const float2*)(smem + S_V);

    for (int ln = 0; ln < 4; ln++) {
        unsigned byte = (mbytes >> (ln * 8)) & 0xffu;

        float2 fR[16], fP[16];
#pragma unroll
        for (int k = 0; k < 8; k++) {
            // cp = pre-enc layer2 output at (t+1) for feature (nb+ln)*8+k
            const float4* w4 = (const float4*)(smem + S_PW2T + (ln * 8 + k) * 8);
            float4 wa = w4[0], wb = w4[1];
            float cp = smem[S_PB2 + ln * 8 + k];
            cp = fmaf(h1p[0], wa.x, cp); cp = fmaf(h1p[1], wa.y, cp);
            cp = fmaf(h1p[2], wa.z, cp); cp = fmaf(h1p[3], wa.w, cp);
            cp = fmaf(h1p[4], wb.x, cp); cp = fmaf(h1p[5], wb.y, cp);
            cp = fmaf(h1p[6], wb.z, cp); cp = fmaf(h1p[7], wb.w, cp);
            float2 cp2 = make_float2(cp, cp);
            float2 Vk = sv[k * QB + tid];
            bool on = (byte >> k) & 1u;
            fR[k]     = on ? M[k] : zz;
            fR[8 + k] = on ? Vk : zz;
            fP[k]     = fmul2(cp2, M[k]);
            fP[8 + k] = fmul2(cp2, Vk);
        }

        float outR = 0.f, outP = 0.f;
        const float4* w4base = (const float4*)(smem + S_W0 + ln * 2048);
        const float2* bw = (const float2*)(smem + S_BW + 2 * ln * 64);
#pragma unroll 2
        for (int j = 0; j < 64; j++) {
            const float4* w4 = w4base + j * 8;
            float2 aR0 = zz, aR1 = zz, aP0 = zz, aP1 = zz;
#pragma unroll
            for (int qq = 0; qq < 8; qq++) {
                float4 wA = w4[qq];
                float2 w0p = make_float2(wA.x, wA.y);
                float2 w1p = make_float2(wA.z, wA.w);
                aR0 = ffma2(fR[2 * qq],     w0p, aR0);
                aR1 = ffma2(fR[2 * qq + 1], w1p, aR1);
                aP0 = ffma2(fP[2 * qq],     w0p, aP0);
                aP1 = ffma2(fP[2 * qq + 1], w1p, aP1);
            }
            float2 bwj = bw[j];
            float2 sR = fadd2(aR0, aR1);
            float2 sP = fadd2(aP0, aP1);
            float hR = fmaxf(sR.x + sR.y + bwj.x, 0.f);
            float hP = fmaxf(sP.x + sP.y + bwj.x, 0.f);
            outR = fmaf(hR, bwj.y, outR);
            outP = fmaf(hP, bwj.y, outP);
        }
        float be = smem[S_BEFF + ln];
        out[OFF_RECON + (size_t)t * 16 + nb + ln] = fmaxf(outR + be, 0.f);
        if (hasP)
            out[OFF_PRED + (size_t)(t + 1) * 16 + nb + ln] = fmaxf(outP + be, 0.f);
    }
}

// ---------------------------------------------------------------------------
extern "C" void kernel_launch(void* const* d_in, const int* in_sizes, int n_in,
                              void* d_out, int out_size) {
    const float* lm  = (const float*)d_in[0];
    const float* lv  = (const float*)d_in[1];
    const float* Tin = (const float*)d_in[2];
    const float* cw0 = (const float*)d_in[3];
    const float* cb0 = (const float*)d_in[4];
    const float* cw1 = (const float*)d_in[5];
    const float* cb1 = (const float*)d_in[6];
    const float* cw2 = (const float*)d_in[7];
    const float* cb2 = (const float*)d_in[8];
    const float* pw0 = (const float*)d_in[9];
    const float* pb0 = (const float*)d_in[10];
    const float* pw1 = (const float*)d_in[11];
    const float* pb1 = (const float*)d_in[12];
    const float* pw2 = (const float*)d_in[13];
    const float* pb2 = (const float*)d_in[14];
    const float* fmw1 = (const float*)d_in[15];
    const float* fmb1 = (const float*)d_in[16];
    const float* fmw2 = (const float*)d_in[17];
    const float* fmb2 = (const float*)d_in[18];
    const float* fvw1 = (const float*)d_in[19];
    const float* fvb1 = (const float*)d_in[20];
    const float* fvw2 = (const float*)d_in[21];
    const float* fvb2 = (const float*)d_in[22];
    const float* lw0 = (const float*)d_in[23];
    const float* lb0 = (const float*)d_in[24];
    const float* lw1 = (const float*)d_in[25];
    const float* lb1 = (const float*)d_in[26];
    const float* lw2 = (const float*)d_in[27];
    const float* lb2 = (const float*)d_in[28];
    float* out = (float*)d_out;

    cudaFuncSetAttribute(mega_kernel, cudaFuncAttributeMaxDynamicSharedMemorySize,
                         MEGA_SMEM_BYTES);

    prep_kernel<<<1, 1024>>>(lw0, lw1, lw2, lb0, lb1, lb2, out);
    dim3 grid(QGX, 4);
    mega_kernel<<<grid, QB, MEGA_SMEM_BYTES>>>(
        lm, lv, Tin,
        cw0, cb0, cw1, cb1, cw2, cb2,
        pw0, pb0, pw1, pb1, pw2, pb2,
        fmw1, fmb1, fmw2, fmb2,
        fvw1, fvb1, fvw2, fvb2,
        lb0, out);
}